// round 16
// baseline (speedup 1.0000x reference)
#include <cuda_runtime.h>
#include <cuda_bf16.h>
#include <cuda_fp16.h>
#include <cstdint>

#define NTOK 8192
#define DIN  1024
#define DH   128

// Pre-split inputs (prep kernel).
__device__ __nv_bfloat16 g_Xhi[NTOK * DIN], g_Xlo[NTOK * DIN];
__device__ __nv_bfloat16 g_Whi[3 * DIN * DH], g_Wlo[3 * DIN * DH];
// Split operands produced by the projection kernel.
__device__ __nv_bfloat16 g_Qhi[NTOK * DH], g_Qlo[NTOK * DH]; // pre-scaled by (1/sqrt d)*log2 e
__device__ __nv_bfloat16 g_Khi[NTOK * DH], g_Klo[NTOK * DH];
__device__ __half        g_Vhi[NTOK * DH];

// Flat-scheduled flash partials: 148 CTAs x <=2 segments (slot = 2*cta + seg).
#define NCTA_F 148
#define NSEG (2 * NCTA_F)            // 296
#define BMF 192                       // rows per Q-block (12 warps x 16)
#define NQB 43                        // ceil(8192 / 192)
#define FTILES (NQB * 128)            // 5504 flat (Q-block, key-tile) units
__device__ float g_OpartSeg[NSEG * BMF * DH];
__device__ float g_MsegA[NSEG * BMF];
__device__ float g_LsegA[NSEG * BMF];

__device__ __forceinline__ uint32_t smem_u32(const void* p) {
  uint32_t a;
  asm("{ .reg .u64 t; cvta.to.shared.u64 t, %1; cvt.u32.u64 %0, t; }"
      : "=r"(a) : "l"(p));
  return a;
}
__device__ __forceinline__ float ex2f(float x) {
  float y; asm("ex2.approx.ftz.f32 %0, %1;" : "=f"(y) : "f"(x)); return y;
}
__device__ __forceinline__ void ldsm4(uint32_t* r, uint32_t addr) {
  asm volatile("ldmatrix.sync.aligned.m8n8.x4.shared.b16 {%0,%1,%2,%3}, [%4];"
               : "=r"(r[0]), "=r"(r[1]), "=r"(r[2]), "=r"(r[3]) : "r"(addr));
}
__device__ __forceinline__ void ldsm4t(uint32_t* r, uint32_t addr) {
  asm volatile("ldmatrix.sync.aligned.m8n8.x4.trans.shared.b16 {%0,%1,%2,%3}, [%4];"
               : "=r"(r[0]), "=r"(r[1]), "=r"(r[2]), "=r"(r[3]) : "r"(addr));
}
__device__ __forceinline__ void mma_bf16(float* d, const uint32_t* a,
                                         const uint32_t* b) {
  asm volatile(
      "mma.sync.aligned.m16n8k16.row.col.f32.bf16.bf16.f32 "
      "{%0,%1,%2,%3}, {%4,%5,%6,%7}, {%8,%9}, {%0,%1,%2,%3};"
      : "+f"(d[0]), "+f"(d[1]), "+f"(d[2]), "+f"(d[3])
      : "r"(a[0]), "r"(a[1]), "r"(a[2]), "r"(a[3]), "r"(b[0]), "r"(b[1]));
}
__device__ __forceinline__ void mma_f16(float* d, const uint32_t* a,
                                        const uint32_t* b) {
  asm volatile(
      "mma.sync.aligned.m16n8k16.row.col.f32.f16.f16.f32 "
      "{%0,%1,%2,%3}, {%4,%5,%6,%7}, {%8,%9}, {%0,%1,%2,%3};"
      : "+f"(d[0]), "+f"(d[1]), "+f"(d[2]), "+f"(d[3])
      : "r"(a[0]), "r"(a[1]), "r"(a[2]), "r"(a[3]), "r"(b[0]), "r"(b[1]));
}
__device__ __forceinline__ void cpa16(uint32_t dst, const void* src) {
  asm volatile("cp.async.cg.shared.global [%0], [%1], 16;" :: "r"(dst), "l"(src));
}
#define CP_COMMIT() asm volatile("cp.async.commit_group;" ::: "memory")
#define CP_WAIT1() asm volatile("cp.async.wait_group 1;" ::: "memory")
#define CP_WAIT0() asm volatile("cp.async.wait_group 0;" ::: "memory")

// ---------------------------------------------------------------------------
// Prep kernel: split x and W (fp32 -> bf16 hi/lo) in one launch.
// ---------------------------------------------------------------------------
__global__ __launch_bounds__(256) void split_all_kernel(
    const float* __restrict__ x, const float* __restrict__ Wq,
    const float* __restrict__ Wk, const float* __restrict__ Wv) {
  int b = blockIdx.x;
  const float* src;
  __nv_bfloat16 *dhi, *dlo;
  size_t i;
  float sc = 1.0f;
  if (b < NTOK * DIN / 1024) {
    src = x;  dhi = g_Xhi;  dlo = g_Xlo;
    i = ((size_t)b * 256 + threadIdx.x) * 4;
  } else {
    int w = b - NTOK * DIN / 1024;
    int y = w >> 7, bx = w & 127;
    if (y == 0) { src = Wq; sc = 0.08838834764831845f * 1.4426950408889634f; }
    else if (y == 1) src = Wk;
    else src = Wv;
    i = ((size_t)bx * 256 + threadIdx.x) * 4;
    dhi = g_Whi + (size_t)y * DIN * DH;
    dlo = g_Wlo + (size_t)y * DIN * DH;
  }
  float4 v = *(const float4*)(src + i);
  v.x *= sc; v.y *= sc; v.z *= sc; v.w *= sc;
  __nv_bfloat16 h0 = __float2bfloat16_rn(v.x), h1 = __float2bfloat16_rn(v.y);
  __nv_bfloat16 h2 = __float2bfloat16_rn(v.z), h3 = __float2bfloat16_rn(v.w);
  __nv_bfloat162 hh0 = __halves2bfloat162(h0, h1), hh1 = __halves2bfloat162(h2, h3);
  __nv_bfloat162 ll0 = __halves2bfloat162(
      __float2bfloat16_rn(v.x - __bfloat162float(h0)),
      __float2bfloat16_rn(v.y - __bfloat162float(h1)));
  __nv_bfloat162 ll1 = __halves2bfloat162(
      __float2bfloat16_rn(v.z - __bfloat162float(h2)),
      __float2bfloat16_rn(v.w - __bfloat162float(h3)));
  *(uint2*)&dhi[i] = make_uint2(*(uint32_t*)&hh0, *(uint32_t*)&hh1);
  *(uint2*)&dlo[i] = make_uint2(*(uint32_t*)&ll0, *(uint32_t*)&ll1);
}

// ---------------------------------------------------------------------------
// Kernel 1: QKV projection GEMM, BM=192 (12 warps, 384 thr), BK=64.
// grid = (43, 3), one wave, 3 warps/SMSP.  Phase-ordered MMAs (accumulator
// reuse distance 8).
// ---------------------------------------------------------------------------
#define XROW 144
#define WROW 272
#define PXLO 27648
#define PWHI 55296
#define PSTAGE 90112
#define SMEM_PROJ (2 * PSTAGE)
#define PTHR 384

__device__ __forceinline__ void proj_issue(int tid, int mb, int y, int k0,
                                           uint32_t dstbase) {
  // X: items 0..1535 -> Xhi, 1536..3071 -> Xlo (row-clamped).
#pragma unroll
  for (int it = 0; it < 8; it++) {
    int idx = tid + it * PTHR;
    int arr = (idx >= 1536);
    int w = arr ? idx - 1536 : idx;
    int r = w >> 3, c = w & 7;
    int rr = mb + r; if (rr > NTOK - 1) rr = NTOK - 1;
    const __nv_bfloat16* src = (arr ? g_Xlo : g_Xhi) +
                               (size_t)rr * DIN + k0 + c * 8;
    cpa16(dstbase + arr * PXLO + r * XROW + c * 16, src);
  }
  // W: 2 arrays x 64 rows x 16 float4 = 2048 items.
#pragma unroll
  for (int it = 0; it < 6; it++) {
    int idx = tid + it * PTHR;
    if (idx < 2048) {
      int arr = idx >> 10, w = idx & 1023;
      int r = w >> 4, c = w & 15;
      const __nv_bfloat16* src = (arr ? g_Wlo : g_Whi) +
                                 (size_t)y * DIN * DH + (size_t)(k0 + r) * DH + c * 8;
      cpa16(dstbase + PWHI + arr * 17408 + r * WROW + c * 16, src);
    }
  }
}

__global__ __launch_bounds__(PTHR, 1) void qkv_proj_mma() {
  extern __shared__ char smc[];
  const int tid = threadIdx.x;
  const int lane = tid & 31, warp = tid >> 5;
  const int wm = warp * 16;
  const int mb = blockIdx.x * 192;
  const int y = blockIdx.y;
  const uint32_t sb = smem_u32(smc);

  float acc[16][4];
#pragma unroll
  for (int f = 0; f < 16; f++)
#pragma unroll
    for (int e = 0; e < 4; e++) acc[f][e] = 0.f;

  const uint32_t ah_addr = sb + (uint32_t)(wm + (lane & 15)) * XROW +
                           (lane >> 4) * 16;
  const uint32_t bh_addr = sb + PWHI +
                           (uint32_t)((lane & 7) + ((lane >> 3) & 1) * 8) * WROW +
                           ((lane >> 4) & 1) * 16;

  proj_issue(tid, mb, y, 0, sb);           CP_COMMIT();
  proj_issue(tid, mb, y, 64, sb + PSTAGE); CP_COMMIT();

  const int NT = DIN / 64;   // 16
  for (int t = 0; t < NT; t++) {
    if (t + 1 < NT) CP_WAIT1(); else CP_WAIT0();
    __syncthreads();
    uint32_t bo = (uint32_t)(t & 1) * PSTAGE;
#pragma unroll
    for (int j = 0; j < 4; j++) {
      uint32_t ah[4], al[4];
      ldsm4(ah, ah_addr + bo + j * 32);
      ldsm4(al, ah_addr + bo + PXLO + j * 32);
      // Row base for this K-chunk; hx selects column group (bytes!).
#pragma unroll
      for (int hx = 0; hx < 2; hx++) {
        uint32_t base = bh_addr + bo + (uint32_t)(j * 16) * WROW + hx * 128;
        uint32_t b0[4], b1[4], b2[4], b3[4];
        ldsm4t(b0, base);
        ldsm4t(b1, base + 32);
        ldsm4t(b2, base + 64);
        ldsm4t(b3, base + 96);
        float (*A)[4] = acc + 8 * hx;
        mma_bf16(A[0], ah, b0); mma_bf16(A[1], ah, b0 + 2);
        mma_bf16(A[2], ah, b1); mma_bf16(A[3], ah, b1 + 2);
        mma_bf16(A[4], ah, b2); mma_bf16(A[5], ah, b2 + 2);
        mma_bf16(A[6], ah, b3); mma_bf16(A[7], ah, b3 + 2);
        mma_bf16(A[0], al, b0); mma_bf16(A[1], al, b0 + 2);
        mma_bf16(A[2], al, b1); mma_bf16(A[3], al, b1 + 2);
        mma_bf16(A[4], al, b2); mma_bf16(A[5], al, b2 + 2);
        mma_bf16(A[6], al, b3); mma_bf16(A[7], al, b3 + 2);
        uint32_t c0[4], c1[4], c2[4], c3[4];
        ldsm4t(c0, base + 17408);
        ldsm4t(c1, base + 17408 + 32);
        ldsm4t(c2, base + 17408 + 64);
        ldsm4t(c3, base + 17408 + 96);
        mma_bf16(A[0], ah, c0); mma_bf16(A[1], ah, c0 + 2);
        mma_bf16(A[2], ah, c1); mma_bf16(A[3], ah, c1 + 2);
        mma_bf16(A[4], ah, c2); mma_bf16(A[5], ah, c2 + 2);
        mma_bf16(A[6], ah, c3); mma_bf16(A[7], ah, c3 + 2);
      }
    }
    __syncthreads();
    if (t + 2 < NT) { proj_issue(tid, mb, y, (t + 2) * 64, sb + bo); }
    CP_COMMIT();
  }

  int r0 = mb + wm + (lane >> 2), r1 = r0 + 8;
  int cb = 2 * (lane & 3);
#pragma unroll
  for (int f = 0; f < 16; f++) {
    int c = 8 * f + cb;
    float v0 = acc[f][0], v1 = acc[f][1], v2 = acc[f][2], v3 = acc[f][3];
    if (y == 2) {
      if (r0 < NTOK)
        *(__half2*)&g_Vhi[(size_t)r0 * DH + c] = __floats2half2_rn(v0, v1);
      if (r1 < NTOK)
        *(__half2*)&g_Vhi[(size_t)r1 * DH + c] = __floats2half2_rn(v2, v3);
    } else {
      __nv_bfloat16* hi = y ? g_Khi : g_Qhi;
      __nv_bfloat16* lo = y ? g_Klo : g_Qlo;
      if (r0 < NTOK) {
        __nv_bfloat16 h0 = __float2bfloat16_rn(v0), h1 = __float2bfloat16_rn(v1);
        *(__nv_bfloat162*)&hi[(size_t)r0 * DH + c] = __halves2bfloat162(h0, h1);
        *(__nv_bfloat162*)&lo[(size_t)r0 * DH + c] = __halves2bfloat162(
            __float2bfloat16_rn(v0 - __bfloat162float(h0)),
            __float2bfloat16_rn(v1 - __bfloat162float(h1)));
      }
      if (r1 < NTOK) {
        __nv_bfloat16 h2 = __float2bfloat16_rn(v2), h3 = __float2bfloat16_rn(v3);
        *(__nv_bfloat162*)&hi[(size_t)r1 * DH + c] = __halves2bfloat162(h2, h3);
        *(__nv_bfloat162*)&lo[(size_t)r1 * DH + c] = __halves2bfloat162(
            __float2bfloat16_rn(v2 - __bfloat162float(h2)),
            __float2bfloat16_rn(v3 - __bfloat162float(h3)));
      }
    }
  }
}

// ---------------------------------------------------------------------------
// Kernel 2: flash attention, BM=192 (12 warps, 384 threads), BN=64,
// flat-scheduled over 148 CTAs.  Phase-ordered MMAs in S and PV.
// ---------------------------------------------------------------------------
#define ROWB 272
#define SKLO 17408
#define SVHI 34816
#define FSTAGE 52224
#define QOFF (2 * FSTAGE)
#define SMEM_FLASH (4 * FSTAGE)
#define FTHR 384

__device__ __forceinline__ void flash_issue(int tid, int n0, uint32_t dstbase) {
#pragma unroll
  for (int it = 0; it < 8; it++) {
    int idx = tid + it * FTHR;
    int arr = idx >> 10, w = idx & 1023;
    int r = w >> 4, c = w & 15;
    const __nv_bfloat16* srcb;
    if (arr == 0)      srcb = g_Khi;
    else if (arr == 1) srcb = g_Klo;
    else               srcb = (const __nv_bfloat16*)g_Vhi;
    cpa16(dstbase + arr * 17408 + r * ROWB + c * 16,
          srcb + (size_t)(n0 + r) * DH + c * 8);
  }
}

// S = Q K^T with phase-ordered MMAs (accumulator reuse distance 8).
__device__ __forceinline__ void s_mma_tile(float sf[8][4], uint32_t kbase,
                                           uint32_t qh_addr, uint32_t ql_addr) {
#pragma unroll
  for (int f = 0; f < 8; f++)
#pragma unroll
    for (int e = 0; e < 4; e++) sf[f][e] = 0.f;
#pragma unroll
  for (int j = 0; j < 8; j++) {
    uint32_t qh[4], ql[4];
    ldsm4(qh, qh_addr + j * 32);
    ldsm4(ql, ql_addr + j * 32);
    uint32_t b0[4], b1[4], b2[4], b3[4];
    uint32_t base = kbase + j * 32;
    ldsm4(b0, base);
    ldsm4(b1, base + (uint32_t)16 * ROWB);
    ldsm4(b2, base + (uint32_t)32 * ROWB);
    ldsm4(b3, base + (uint32_t)48 * ROWB);
    mma_bf16(sf[0], qh, b0); mma_bf16(sf[1], qh, b0 + 2);
    mma_bf16(sf[2], qh, b1); mma_bf16(sf[3], qh, b1 + 2);
    mma_bf16(sf[4], qh, b2); mma_bf16(sf[5], qh, b2 + 2);
    mma_bf16(sf[6], qh, b3); mma_bf16(sf[7], qh, b3 + 2);
    mma_bf16(sf[0], ql, b0); mma_bf16(sf[1], ql, b0 + 2);
    mma_bf16(sf[2], ql, b1); mma_bf16(sf[3], ql, b1 + 2);
    mma_bf16(sf[4], ql, b2); mma_bf16(sf[5], ql, b2 + 2);
    mma_bf16(sf[6], ql, b3); mma_bf16(sf[7], ql, b3 + 2);
    uint32_t c0[4], c1[4], c2[4], c3[4];
    ldsm4(c0, base + SKLO);
    ldsm4(c1, base + SKLO + (uint32_t)16 * ROWB);
    ldsm4(c2, base + SKLO + (uint32_t)32 * ROWB);
    ldsm4(c3, base + SKLO + (uint32_t)48 * ROWB);
    mma_bf16(sf[0], qh, c0); mma_bf16(sf[1], qh, c0 + 2);
    mma_bf16(sf[2], qh, c1); mma_bf16(sf[3], qh, c1 + 2);
    mma_bf16(sf[4], qh, c2); mma_bf16(sf[5], qh, c2 + 2);
    mma_bf16(sf[6], qh, c3); mma_bf16(sf[7], qh, c3 + 2);
  }
}

__device__ __forceinline__ void softmax_pv(float sf[8][4], float of[16][4],
                                           float& mrow0, float& mrow1,
                                           float& l0, float& l1,
                                           uint32_t vbase) {
  float mx0 = sf[0][0], mx1 = sf[0][2];
#pragma unroll
  for (int f = 0; f < 8; f++) {
    mx0 = fmaxf(mx0, fmaxf(sf[f][0], sf[f][1]));
    mx1 = fmaxf(mx1, fmaxf(sf[f][2], sf[f][3]));
  }
  mx0 = fmaxf(mx0, __shfl_xor_sync(0xffffffffu, mx0, 1));
  mx0 = fmaxf(mx0, __shfl_xor_sync(0xffffffffu, mx0, 2));
  mx1 = fmaxf(mx1, __shfl_xor_sync(0xffffffffu, mx1, 1));
  mx1 = fmaxf(mx1, __shfl_xor_sync(0xffffffffu, mx1, 2));

  float mn0 = fmaxf(mrow0, mx0), mn1 = fmaxf(mrow1, mx1);
  float a0 = ex2f(mrow0 - mn0), a1 = ex2f(mrow1 - mn1);
  mrow0 = mn0; mrow1 = mn1;

  float s0 = 0.f, s1 = 0.f;
#pragma unroll
  for (int f = 0; f < 8; f++) {
    sf[f][0] = ex2f(sf[f][0] - mn0);
    sf[f][1] = ex2f(sf[f][1] - mn0);
    sf[f][2] = ex2f(sf[f][2] - mn1);
    sf[f][3] = ex2f(sf[f][3] - mn1);
    s0 += sf[f][0] + sf[f][1];
    s1 += sf[f][2] + sf[f][3];
  }
  s0 += __shfl_xor_sync(0xffffffffu, s0, 1);
  s0 += __shfl_xor_sync(0xffffffffu, s0, 2);
  s1 += __shfl_xor_sync(0xffffffffu, s1, 1);
  s1 += __shfl_xor_sync(0xffffffffu, s1, 2);
  l0 = l0 * a0 + s0;
  l1 = l1 * a1 + s1;

  if (!__all_sync(0xffffffffu, (__float_as_uint(a0) == 0x3f800000u) &&
                              (__float_as_uint(a1) == 0x3f800000u))) {
#pragma unroll
    for (int f = 0; f < 16; f++) {
      of[f][0] *= a0;  of[f][1] *= a0;
      of[f][2] *= a1;  of[f][3] *= a1;
    }
  }

  // PV with phase-ordered MMAs (8 distinct accumulators per phase).
#pragma unroll
  for (int j2 = 0; j2 < 4; j2++) {
    uint32_t ph[4];
    __half2 h;
    h = __floats2half2_rn(sf[2 * j2][0], sf[2 * j2][1]);         ph[0] = *(uint32_t*)&h;
    h = __floats2half2_rn(sf[2 * j2][2], sf[2 * j2][3]);         ph[1] = *(uint32_t*)&h;
    h = __floats2half2_rn(sf[2 * j2 + 1][0], sf[2 * j2 + 1][1]); ph[2] = *(uint32_t*)&h;
    h = __floats2half2_rn(sf[2 * j2 + 1][2], sf[2 * j2 + 1][3]); ph[3] = *(uint32_t*)&h;
    uint32_t ka = vbase + (uint32_t)(j2 * 16) * ROWB;
#pragma unroll
    for (int hx = 0; hx < 2; hx++) {
      uint32_t v0[4], v1[4], v2[4], v3[4];
      uint32_t a = ka + hx * 128;
      ldsm4t(v0, a);
      ldsm4t(v1, a + 32);
      ldsm4t(v2, a + 64);
      ldsm4t(v3, a + 96);
      float (*O)[4] = of + 8 * hx;
      mma_f16(O[0], ph, v0); mma_f16(O[1], ph, v0 + 2);
      mma_f16(O[2], ph, v1); mma_f16(O[3], ph, v1 + 2);
      mma_f16(O[4], ph, v2); mma_f16(O[5], ph, v2 + 2);
      mma_f16(O[6], ph, v3); mma_f16(O[7], ph, v3 + 2);
    }
  }
}

__global__ __launch_bounds__(FTHR, 1) void flash_mma(int dummy) {
  extern __shared__ char smc[];
  const int tid = threadIdx.x;
  const int lane = tid & 31, warp = tid >> 5;
  const int wm = warp * 16;
  const int cta = blockIdx.x;
  const uint32_t sb = smem_u32(smc);

  const int Tstart = (cta * FTILES) / NCTA_F;
  const int Tend = ((cta + 1) * FTILES) / NCTA_F;

  flash_issue(tid, (Tstart & 127) * 64, sb);                CP_COMMIT();
  flash_issue(tid, ((Tstart + 1) & 127) * 64, sb + FSTAGE); CP_COMMIT();

  const uint32_t qh_addr = sb + QOFF + (uint32_t)(wm + (lane & 15)) * ROWB +
                           (lane >> 4) * 16;
  const uint32_t ql_addr = qh_addr + FSTAGE;
  const uint32_t kaddr = sb + (uint32_t)((lane & 7) + ((lane >> 4) << 3)) * ROWB +
                         ((lane >> 3) & 1) * 16;
  const uint32_t vaddr = sb + (uint32_t)((lane & 7) + (((lane >> 3) & 1) << 3)) * ROWB +
                         ((lane >> 4) & 1) * 16 + SVHI;

  float of[16][4];
  float mrow0 = -1e30f, mrow1 = -1e30f, l0 = 0.f, l1 = 0.f;
  int curblk = -1, seg = 0;

  const int r0 = lane >> 2, r1 = r0 + 8;
  const int cbase = 2 * (lane & 3);

  for (int t = Tstart; t < Tend; t++) {
    if (t < Tend - 1) CP_WAIT1(); else CP_WAIT0();
    __syncthreads();

    int qb = t >> 7;
    if (qb != curblk) {
      if (curblk >= 0) {
        int slot = cta * 2 + seg;
        float* Ob = g_OpartSeg + (size_t)slot * BMF * DH;
        int lr0 = wm + r0, lr1 = wm + r1;
#pragma unroll
        for (int f = 0; f < 16; f++) {
          *(float2*)&Ob[lr0 * DH + 8 * f + cbase] = make_float2(of[f][0], of[f][1]);
          *(float2*)&Ob[lr1 * DH + 8 * f + cbase] = make_float2(of[f][2], of[f][3]);
        }
        if ((lane & 3) == 0) {
          g_MsegA[slot * BMF + lr0] = mrow0;  g_LsegA[slot * BMF + lr0] = l0;
          g_MsegA[slot * BMF + lr1] = mrow1;  g_LsegA[slot * BMF + lr1] = l1;
        }
        seg = 1;
      }
      curblk = qb;
#pragma unroll
      for (int it = 0; it < 16; it++) {
        int idx = tid + it * FTHR;
        int arr = idx >= BMF * 16;
        int w = arr ? idx - BMF * 16 : idx;
        int r = w >> 4, c = w & 15;
        int rr = curblk * BMF + r;
        if (rr > NTOK - 1) rr = NTOK - 1;
        const __nv_bfloat16* src = arr ? g_Qlo : g_Qhi;
        *(float4*)(smc + QOFF + arr * FSTAGE + r * ROWB + c * 16) =
            *(const float4*)(src + (size_t)rr * DH + c * 8);
      }
      __syncthreads();
#pragma unroll
      for (int f = 0; f < 16; f++)
#pragma unroll
        for (int e = 0; e < 4; e++) of[f][e] = 0.f;
      mrow0 = -1e30f; mrow1 = -1e30f; l0 = 0.f; l1 = 0.f;
    }

    const uint32_t bo = (uint32_t)((t - Tstart) & 1) * FSTAGE;

    float sf[8][4];
    s_mma_tile(sf, kaddr + bo, qh_addr, ql_addr);
    softmax_pv(sf, of, mrow0, mrow1, l0, l1, vaddr + bo);

    __syncthreads();
    if (t + 2 < Tend) {
      flash_issue(tid, ((t + 2) & 127) * 64, sb + bo);
    }
    CP_COMMIT();
  }

  {
    int slot = cta * 2 + seg;
    float* Ob = g_OpartSeg + (size_t)slot * BMF * DH;
    int lr0 = wm + r0, lr1 = wm + r1;
#pragma unroll
    for (int f = 0; f < 16; f++) {
      *(float2*)&Ob[lr0 * DH + 8 * f + cbase] = make_float2(of[f][0], of[f][1]);
      *(float2*)&Ob[lr1 * DH + 8 * f + cbase] = make_float2(of[f][2], of[f][3]);
    }
    if ((lane & 3) == 0) {
      g_MsegA[slot * BMF + lr0] = mrow0;  g_LsegA[slot * BMF + lr0] = l0;
      g_MsegA[slot * BMF + lr1] = mrow1;  g_LsegA[slot * BMF + lr1] = l1;
    }
  }
}

// ---------------------------------------------------------------------------
// Kernel 3: merge — analytic slot enumeration for BM=192 blocks.
// ---------------------------------------------------------------------------
__global__ __launch_bounds__(256) void merge_kernel(float* __restrict__ out) {
  const int tid = threadIdx.x;
  const int row = blockIdx.x * 8 + (tid >> 5);
  const int q = row / BMF;
  const int lrow = row - q * BMF;
  const int c4 = (tid & 31) * 4;

  const int t0 = q * 128, t1 = t0 + 128;

  float m = -1e30f, l = 0.f;
  float4 O = make_float4(0.f, 0.f, 0.f, 0.f);

  int i = (t0 * NCTA_F) / FTILES;
#pragma unroll 1
  for (; i < NCTA_F; i++) {
    int ts = (i * FTILES) / NCTA_F;
    if (ts >= t1) break;
    int te = ((i + 1) * FTILES) / NCTA_F;
    if (te <= t0) continue;
    int slot = 2 * i + (((ts >> 7) == q) ? 0 : 1);

    float ms = g_MsegA[slot * BMF + lrow];
    float ls = g_LsegA[slot * BMF + lrow];
    float4 Os = *(const float4*)&g_OpartSeg[(size_t)slot * BMF * DH +
                                            lrow * DH + c4];
    float mn = fmaxf(m, ms);
    float wa = ex2f(m - mn), wb = ex2f(ms - mn);
    O.x = O.x * wa + Os.x * wb;
    O.y = O.y * wa + Os.y * wb;
    O.z = O.z * wa + Os.z * wb;
    O.w = O.w * wa + Os.w * wb;
    l = l * wa + ls * wb;
    m = mn;
  }

  float inv = 1.0f / l;
  float4 r = make_float4(O.x * inv, O.y * inv, O.z * inv, O.w * inv);
  *(float4*)&out[(size_t)row * DH + c4] = r;
}

// ---------------------------------------------------------------------------
extern "C" void kernel_launch(void* const* d_in, const int* in_sizes, int n_in,
                              void* d_out, int out_size) {
  const float* x  = (const float*)d_in[0];
  const float* Wq = (const float*)d_in[1];
  const float* Wk = (const float*)d_in[2];
  const float* Wv = (const float*)d_in[3];
  float* out = (float*)d_out;

  split_all_kernel<<<NTOK * DIN / 1024 + 3 * (DIN * DH / 1024), 256>>>(
      x, Wq, Wk, Wv);

  cudaFuncSetAttribute(qkv_proj_mma, cudaFuncAttributeMaxDynamicSharedMemorySize,
                       SMEM_PROJ);
  qkv_proj_mma<<<dim3(NQB, 3, 1), PTHR, SMEM_PROJ>>>();

  cudaFuncSetAttribute(flash_mma, cudaFuncAttributeMaxDynamicSharedMemorySize,
                       SMEM_FLASH);
  flash_mma<<<NCTA_F, FTHR, SMEM_FLASH>>>(0);

  merge_kernel<<<NTOK / 8, 256>>>(out);
}